// round 7
// baseline (speedup 1.0000x reference)
#include <cuda_runtime.h>
#include <cuda_bf16.h>
#include <math.h>

// Problem constants
#define B 4096
#define K 128
#define C 100
#define MARGIN 0.3f

#define PW_BLOCKS ((32 * 33) / 2)   // 528 triangular 128x128 tiles
#define CE_ROWS 16
#define CE_BLOCKS (B / CE_ROWS)     // 256
#define TOTAL_BLOCKS (PW_BLOCKS + CE_BLOCKS)

typedef unsigned long long u64;

// Scratch (device globals). maxbits/minbits initialized by memset nodes:
// 0x00000000 = 0.0f, 0x7f7f7f7f = 3.39e38f (greater than any real d^2).
__device__ int      g_maxbits[B];
__device__ int      g_minbits[B];
__device__ float    g_ce[B];
__device__ unsigned g_done;

// ---------------------------------------------------------------------------
// Pairwise body: triangular Gram tile + fused triplet epilogue.
// Row norms computed in-block (warp-shuffle during tile load).
// ---------------------------------------------------------------------------
#define PAD 130
#define PW_SMEM (2 * 128 * PAD * 4)

__device__ __forceinline__ void pairwise_body(float* sm, const float* __restrict__ emb,
                                              const int* __restrict__ labels, int bid) {
    float* As = sm;                 // [128][130]
    float* Bs = sm + 128 * PAD;     // [128][130]
    __shared__ int   labA[128], labB[128];
    __shared__ float sqA[128], sqB[128];
    __shared__ float s_cp[8][128], s_cn[8][128];

    // Triangular block decode: by <= bx
    float tf = sqrtf(8.0f * (float)bid + 1.0f);
    int bx = (int)((tf - 1.0f) * 0.5f);
    while ((bx + 1) * (bx + 2) / 2 <= bid) bx++;
    while (bx * (bx + 1) / 2 > bid) bx--;
    int by = bid - bx * (bx + 1) / 2;
    const bool diag = (by == bx);

    const int tx   = threadIdx.x & 15, ty = threadIdx.x >> 4;
    const int tid  = threadIdx.x;
    const int wid  = tid >> 5;
    const int lane = tid & 31;
    const int i0   = by * 128;
    const int j0   = bx * 128;

    // Tile load: warp w loads row w + 8*iter entirely (32 lanes x float4).
    // Warp-shuffle sum of v·v gives the row's squared norm for free.
    const float4* e4 = reinterpret_cast<const float4*>(emb);
    #pragma unroll
    for (int it = 0; it < 16; it++) {
        int row = wid + it * 8;
        float4 va = e4[(i0 + row) * 32 + lane];
        float4 vb = e4[(j0 + row) * 32 + lane];
        float2* ap = reinterpret_cast<float2*>(&As[row * PAD + lane * 4]);
        ap[0] = make_float2(va.x, va.y);
        ap[1] = make_float2(va.z, va.w);
        float2* bp = reinterpret_cast<float2*>(&Bs[row * PAD + lane * 4]);
        bp[0] = make_float2(vb.x, vb.y);
        bp[1] = make_float2(vb.z, vb.w);
        float sa = va.x * va.x + va.y * va.y + va.z * va.z + va.w * va.w;
        float sb = vb.x * vb.x + vb.y * vb.y + vb.z * vb.z + vb.w * vb.w;
        #pragma unroll
        for (int m = 16; m; m >>= 1) {
            sa += __shfl_xor_sync(0xffffffffu, sa, m);
            sb += __shfl_xor_sync(0xffffffffu, sb, m);
        }
        if (lane == 0) { sqA[row] = sa; sqB[row] = sb; }
    }
    if (tid < 128) {
        labA[tid] = labels[i0 + tid];
        labB[tid] = labels[j0 + tid];
    }
    __syncthreads();

    u64 acc[8][8];
    #pragma unroll
    for (int q = 0; q < 8; q++)
        #pragma unroll
        for (int r = 0; r < 8; r++) acc[q][r] = 0ull;

    #pragma unroll 2
    for (int kp = 0; kp < K / 2; kp++) {
        u64 a2[8], b2[8];
        #pragma unroll
        for (int q = 0; q < 8; q++)
            a2[q] = *reinterpret_cast<const u64*>(&As[(ty + 16 * q) * PAD + 2 * kp]);
        #pragma unroll
        for (int r = 0; r < 8; r++)
            b2[r] = *reinterpret_cast<const u64*>(&Bs[(tx + 16 * r) * PAD + 2 * kp]);
        #pragma unroll
        for (int q = 0; q < 8; q++)
            #pragma unroll
            for (int r = 0; r < 8; r++)
                asm("fma.rn.f32x2 %0, %1, %2, %0;"
                    : "+l"(acc[q][r]) : "l"(a2[q]), "l"(b2[r]));
    }

    const float INF = 3.0e38f;
    float colPos[8], colNeg[8];
    #pragma unroll
    for (int r = 0; r < 8; r++) { colPos[r] = 0.0f; colNeg[r] = INF; }

    #pragma unroll
    for (int q = 0; q < 8; q++) {
        int   i  = ty + 16 * q;
        int   li = labA[i];
        float si = sqA[i];
        float pos = 0.0f, neg = INF;
        #pragma unroll
        for (int r = 0; r < 8; r++) {
            int   j   = tx + 16 * r;
            float glo = __uint_as_float((unsigned)(acc[q][r] & 0xffffffffull));
            float ghi = __uint_as_float((unsigned)(acc[q][r] >> 32));
            float d2  = fmaxf(si + sqB[j] - 2.0f * (glo + ghi), 0.0f);
            bool same = (labB[j] == li);
            if (same) { pos = fmaxf(pos, d2); colPos[r] = fmaxf(colPos[r], d2); }
            else      { neg = fminf(neg, d2); colNeg[r] = fminf(colNeg[r], d2); }
        }
        #pragma unroll
        for (int m = 8; m; m >>= 1) {
            pos = fmaxf(pos, __shfl_xor_sync(0xffffffffu, pos, m));
            neg = fminf(neg, __shfl_xor_sync(0xffffffffu, neg, m));
        }
        if (tx == 0) {
            atomicMax(&g_maxbits[i0 + i], __float_as_int(pos));
            atomicMin(&g_minbits[i0 + i], __float_as_int(neg));
        }
    }

    if (!diag) {
        #pragma unroll
        for (int r = 0; r < 8; r++) {
            float p = fmaxf(colPos[r], __shfl_xor_sync(0xffffffffu, colPos[r], 16));
            float n = fminf(colNeg[r], __shfl_xor_sync(0xffffffffu, colNeg[r], 16));
            if ((tid & 16) == 0) {
                s_cp[wid][r * 16 + tx] = p;
                s_cn[wid][r * 16 + tx] = n;
            }
        }
        __syncthreads();
        if (tid < 128) {
            float p = s_cp[0][tid], n = s_cn[0][tid];
            #pragma unroll
            for (int w = 1; w < 8; w++) {
                p = fmaxf(p, s_cp[w][tid]);
                n = fminf(n, s_cn[w][tid]);
            }
            atomicMax(&g_maxbits[j0 + tid], __float_as_int(p));
            atomicMin(&g_minbits[j0 + tid], __float_as_int(n));
        }
    }
}

// ---------------------------------------------------------------------------
// CE body: 256 threads, two class-groups of 100 threads x 8 rows each.
// ---------------------------------------------------------------------------
__device__ __forceinline__ void ce_body(float* sm, const float* __restrict__ emb,
                                        const int* __restrict__ labels,
                                        const float* __restrict__ w,
                                        const float* __restrict__ bias, int bid) {
    float* w_s = sm;                        // [100][133]
    float* e_s = sm + C * 133;              // [16][129]
    float* lg  = e_s + CE_ROWS * 129;       // [16][100]

    int tid = threadIdx.x;
    int r0  = bid * CE_ROWS;

    for (int f = tid; f < C * K; f += 256) {
        int c = f >> 7, k = f & 127;
        w_s[c * 133 + k] = w[f];
    }
    for (int f = tid; f < CE_ROWS * K; f += 256) {
        int r = f >> 7, k = f & 127;
        e_s[r * 129 + k] = emb[(r0 + r) * K + k];
    }
    __syncthreads();

    int grp = tid >> 7;
    int c   = tid & 127;
    if (c < C) {
        float accv[8];
        float bv = bias[c];
        #pragma unroll
        for (int r = 0; r < 8; r++) accv[r] = bv;
        for (int k = 0; k < K; k++) {
            float wv = w_s[c * 133 + k];
            #pragma unroll
            for (int r = 0; r < 8; r++)
                accv[r] = fmaf(wv, e_s[(grp * 8 + r) * 129 + k], accv[r]);
        }
        #pragma unroll
        for (int r = 0; r < 8; r++) lg[(grp * 8 + r) * C + c] = accv[r];
    }
    __syncthreads();

    if (tid < CE_ROWS) {
        int   lab = labels[r0 + tid];
        float m = -1e30f;
        for (int cc = 0; cc < C; cc++) m = fmaxf(m, lg[tid * C + cc]);
        float s = 0.0f;
        for (int cc = 0; cc < C; cc++) s += expf(lg[tid * C + cc] - m);
        g_ce[r0 + tid] = m + logf(s) - lg[tid * C + lab];
    }
}

// ---------------------------------------------------------------------------
// Fused kernel + last-block-done final reduction (deterministic fixed tree).
// ---------------------------------------------------------------------------
__global__ void __launch_bounds__(256, 1)
fused_kernel(const float* __restrict__ emb, const int* __restrict__ labels,
             const float* __restrict__ w, const float* __restrict__ bias,
             float* __restrict__ out) {
    extern __shared__ float sm[];
    if (blockIdx.x < PW_BLOCKS) pairwise_body(sm, emb, labels, blockIdx.x);
    else                        ce_body(sm, emb, labels, w, bias, blockIdx.x - PW_BLOCKS);

    // Signal completion; last block reduces.
    __syncthreads();
    __shared__ unsigned s_last;
    if (threadIdx.x == 0) {
        __threadfence();
        s_last = (atomicAdd(&g_done, 1u) == TOTAL_BLOCKS - 1) ? 1u : 0u;
    }
    __syncthreads();
    if (s_last == 0) return;

    __threadfence();
    int t = threadIdx.x;
    float tr = 0.0f, ce = 0.0f;
    #pragma unroll
    for (int k = 0; k < B / 256; k++) {
        int i = t + k * 256;
        float mx = fmaxf(__int_as_float(__ldcg(&g_maxbits[i])), 1e-12f);
        float mn = fmaxf(__int_as_float(__ldcg(&g_minbits[i])), 1e-12f);
        tr += fmaxf(sqrtf(mx) - sqrtf(mn) + MARGIN, 0.0f);
        ce += __ldcg(&g_ce[i]);
    }
    float* s1 = sm;            // reuse dynamic smem
    float* s2 = sm + 256;
    s1[t] = tr; s2[t] = ce;
    __syncthreads();
    #pragma unroll
    for (int s = 128; s > 0; s >>= 1) {
        if (t < s) { s1[t] += s1[t + s]; s2[t] += s2[t + s]; }
        __syncthreads();
    }
    if (t == 0) out[0] = (s1[0] + s2[0]) * (1.0f / (float)B);
}

// ---------------------------------------------------------------------------
extern "C" void kernel_launch(void* const* d_in, const int* in_sizes, int n_in,
                              void* d_out, int out_size) {
    const float* emb    = (const float*)d_in[0];
    const int*   labels = (const int*)d_in[1];
    const float* fcw    = (const float*)d_in[2];
    const float* fcb    = (const float*)d_in[3];
    float*       out    = (float*)d_out;

    cudaFuncSetAttribute(fused_kernel,
                         cudaFuncAttributeMaxDynamicSharedMemorySize, PW_SMEM);

    void *p_max, *p_min, *p_done;
    cudaGetSymbolAddress(&p_max,  g_maxbits);
    cudaGetSymbolAddress(&p_min,  g_minbits);
    cudaGetSymbolAddress(&p_done, g_done);

    cudaMemsetAsync(p_max,  0x00, B * sizeof(int));   // 0.0f
    cudaMemsetAsync(p_min,  0x7f, B * sizeof(int));   // 3.39e38f (acts as +inf)
    cudaMemsetAsync(p_done, 0x00, sizeof(unsigned));

    fused_kernel<<<TOTAL_BLOCKS, 256, PW_SMEM>>>(emb, labels, fcw, fcb, out);
}

// round 8
// speedup vs baseline: 1.0293x; 1.0293x over previous
#include <cuda_runtime.h>
#include <cuda_bf16.h>
#include <math.h>

// Problem constants
#define B 4096
#define K 128
#define C 100
#define MARGIN 0.3f

#define PW_BLOCKS ((32 * 33) / 2)   // 528 triangular 128x128 tiles
#define CE_ROWS 16
#define CE_BLOCKS (B / CE_ROWS)     // 256
#define TOTAL_BLOCKS (PW_BLOCKS + CE_BLOCKS)

typedef unsigned long long u64;

// Scratch (device globals)
__device__ int      g_maxbits[B];
__device__ int      g_minbits[B];
__device__ float    g_sq[B];
__device__ float    g_ce[B];
__device__ int      g_lab[B];
__device__ unsigned g_done;

// ---------------------------------------------------------------------------
// Kernel 1: squared norms + init + labels (int32).  (exact R6 version)
// ---------------------------------------------------------------------------
__global__ void prep_kernel(const float* __restrict__ emb,
                            const int* __restrict__ labels) {
    int warp = (blockIdx.x * blockDim.x + threadIdx.x) >> 5;
    int lane = threadIdx.x & 31;
    if (warp >= B) return;
    float4 v = reinterpret_cast<const float4*>(emb)[warp * 32 + lane];
    float s = v.x * v.x + v.y * v.y + v.z * v.z + v.w * v.w;
    #pragma unroll
    for (int m = 16; m; m >>= 1) s += __shfl_xor_sync(0xffffffffu, s, m);
    if (lane == 0) {
        g_sq[warp]      = s;
        g_maxbits[warp] = 0;
        g_minbits[warp] = 0x7f800000;   // +inf
        g_lab[warp]     = labels[warp];
    }
}

// ---------------------------------------------------------------------------
// Pairwise body (exact R6 version).
// ---------------------------------------------------------------------------
#define PAD 130
#define PW_SMEM (2 * 128 * PAD * 4)

__device__ __forceinline__ void pairwise_body(float* sm, const float* __restrict__ emb,
                                              int bid) {
    float* As = sm;                 // [128][130]
    float* Bs = sm + 128 * PAD;     // [128][130]
    __shared__ int   labA[128], labB[128];
    __shared__ float sqA[128], sqB[128];
    __shared__ float s_cp[8][128], s_cn[8][128];

    // Triangular block decode: by <= bx
    float tf = sqrtf(8.0f * (float)bid + 1.0f);
    int bx = (int)((tf - 1.0f) * 0.5f);
    while ((bx + 1) * (bx + 2) / 2 <= bid) bx++;
    while (bx * (bx + 1) / 2 > bid) bx--;
    int by = bid - bx * (bx + 1) / 2;
    const bool diag = (by == bx);

    const int tx  = threadIdx.x & 15, ty = threadIdx.x >> 4;
    const int tid = threadIdx.x;
    const int wid = tid >> 5;
    const int i0  = by * 128;
    const int j0  = bx * 128;

    const float4* e4 = reinterpret_cast<const float4*>(emb);
    #pragma unroll
    for (int f = tid; f < 128 * 32; f += 256) {
        int row = f >> 5, c4 = f & 31;
        float4 va = e4[(i0 + row) * 32 + c4];
        float4 vb = e4[(j0 + row) * 32 + c4];
        float2* ap = reinterpret_cast<float2*>(&As[row * PAD + c4 * 4]);
        ap[0] = make_float2(va.x, va.y);
        ap[1] = make_float2(va.z, va.w);
        float2* bp = reinterpret_cast<float2*>(&Bs[row * PAD + c4 * 4]);
        bp[0] = make_float2(vb.x, vb.y);
        bp[1] = make_float2(vb.z, vb.w);
    }
    if (tid < 128) {
        labA[tid] = g_lab[i0 + tid];
        labB[tid] = g_lab[j0 + tid];
        sqA[tid]  = g_sq[i0 + tid];
        sqB[tid]  = g_sq[j0 + tid];
    }
    __syncthreads();

    u64 acc[8][8];
    #pragma unroll
    for (int q = 0; q < 8; q++)
        #pragma unroll
        for (int r = 0; r < 8; r++) acc[q][r] = 0ull;

    #pragma unroll 2
    for (int kp = 0; kp < K / 2; kp++) {
        u64 a2[8], b2[8];
        #pragma unroll
        for (int q = 0; q < 8; q++)
            a2[q] = *reinterpret_cast<const u64*>(&As[(ty + 16 * q) * PAD + 2 * kp]);
        #pragma unroll
        for (int r = 0; r < 8; r++)
            b2[r] = *reinterpret_cast<const u64*>(&Bs[(tx + 16 * r) * PAD + 2 * kp]);
        #pragma unroll
        for (int q = 0; q < 8; q++)
            #pragma unroll
            for (int r = 0; r < 8; r++)
                asm("fma.rn.f32x2 %0, %1, %2, %0;"
                    : "+l"(acc[q][r]) : "l"(a2[q]), "l"(b2[r]));
    }

    const float INF = __int_as_float(0x7f800000);
    float colPos[8], colNeg[8];
    #pragma unroll
    for (int r = 0; r < 8; r++) { colPos[r] = 0.0f; colNeg[r] = INF; }

    #pragma unroll
    for (int q = 0; q < 8; q++) {
        int   i  = ty + 16 * q;
        int   li = labA[i];
        float si = sqA[i];
        float pos = 0.0f, neg = INF;
        #pragma unroll
        for (int r = 0; r < 8; r++) {
            int   j   = tx + 16 * r;
            float glo = __uint_as_float((unsigned)(acc[q][r] & 0xffffffffull));
            float ghi = __uint_as_float((unsigned)(acc[q][r] >> 32));
            float d2  = fmaxf(si + sqB[j] - 2.0f * (glo + ghi), 0.0f);
            bool same = (labB[j] == li);
            if (same) { pos = fmaxf(pos, d2); colPos[r] = fmaxf(colPos[r], d2); }
            else      { neg = fminf(neg, d2); colNeg[r] = fminf(colNeg[r], d2); }
        }
        #pragma unroll
        for (int m = 8; m; m >>= 1) {
            pos = fmaxf(pos, __shfl_xor_sync(0xffffffffu, pos, m));
            neg = fminf(neg, __shfl_xor_sync(0xffffffffu, neg, m));
        }
        if (tx == 0) {
            atomicMax(&g_maxbits[i0 + i], __float_as_int(pos));
            atomicMin(&g_minbits[i0 + i], __float_as_int(neg));
        }
    }

    if (!diag) {
        #pragma unroll
        for (int r = 0; r < 8; r++) {
            float p = fmaxf(colPos[r], __shfl_xor_sync(0xffffffffu, colPos[r], 16));
            float n = fminf(colNeg[r], __shfl_xor_sync(0xffffffffu, colNeg[r], 16));
            if ((tid & 16) == 0) {
                s_cp[wid][r * 16 + tx] = p;
                s_cn[wid][r * 16 + tx] = n;
            }
        }
        __syncthreads();
        if (tid < 128) {
            float p = s_cp[0][tid], n = s_cn[0][tid];
            #pragma unroll
            for (int w = 1; w < 8; w++) {
                p = fmaxf(p, s_cp[w][tid]);
                n = fminf(n, s_cn[w][tid]);
            }
            atomicMax(&g_maxbits[j0 + tid], __float_as_int(p));
            atomicMin(&g_minbits[j0 + tid], __float_as_int(n));
        }
    }
}

// ---------------------------------------------------------------------------
// CE body (exact R6 version).
// ---------------------------------------------------------------------------
__device__ __forceinline__ void ce_body(float* sm, const float* __restrict__ emb,
                                        const float* __restrict__ w,
                                        const float* __restrict__ bias, int bid) {
    float* w_s = sm;                        // [100][133]
    float* e_s = sm + C * 133;              // [16][129]
    float* lg  = e_s + CE_ROWS * 129;       // [16][100]

    int tid = threadIdx.x;
    int r0  = bid * CE_ROWS;

    for (int f = tid; f < C * K; f += 256) {
        int c = f >> 7, k = f & 127;
        w_s[c * 133 + k] = w[f];
    }
    for (int f = tid; f < CE_ROWS * K; f += 256) {
        int r = f >> 7, k = f & 127;
        e_s[r * 129 + k] = emb[(r0 + r) * K + k];
    }
    __syncthreads();

    int grp = tid >> 7;
    int c   = tid & 127;
    if (c < C) {
        float accv[8];
        float bv = bias[c];
        #pragma unroll
        for (int r = 0; r < 8; r++) accv[r] = bv;
        for (int k = 0; k < K; k++) {
            float wv = w_s[c * 133 + k];
            #pragma unroll
            for (int r = 0; r < 8; r++)
                accv[r] = fmaf(wv, e_s[(grp * 8 + r) * 129 + k], accv[r]);
        }
        #pragma unroll
        for (int r = 0; r < 8; r++) lg[(grp * 8 + r) * C + c] = accv[r];
    }
    __syncthreads();

    if (tid < CE_ROWS) {
        int   lab = g_lab[r0 + tid];
        float m = -1e30f;
        for (int cc = 0; cc < C; cc++) m = fmaxf(m, lg[tid * C + cc]);
        float s = 0.0f;
        for (int cc = 0; cc < C; cc++) s += expf(lg[tid * C + cc] - m);
        g_ce[r0 + tid] = m + logf(s) - lg[tid * C + lab];
    }
}

// ---------------------------------------------------------------------------
// Fused kernel; last block performs the deterministic final reduction.
// Tail smem is a distinct static array (no aliasing with dynamic buffer).
// ---------------------------------------------------------------------------
__global__ void __launch_bounds__(256, 1)
fused_kernel(const float* __restrict__ emb, const float* __restrict__ w,
             const float* __restrict__ bias, float* __restrict__ out) {
    extern __shared__ float sm[];
    if (blockIdx.x < PW_BLOCKS) pairwise_body(sm, emb, blockIdx.x);
    else                        ce_body(sm, emb, w, bias, blockIdx.x - PW_BLOCKS);

    __shared__ unsigned s_last;
    __shared__ float    s1[256], s2[256];
    __syncthreads();
    if (threadIdx.x == 0) {
        __threadfence();
        s_last = (atomicAdd(&g_done, 1u) == TOTAL_BLOCKS - 1) ? 1u : 0u;
    }
    __syncthreads();
    if (s_last == 0) return;

    __threadfence();
    int t = threadIdx.x;
    float tr = 0.0f, ce = 0.0f;
    #pragma unroll
    for (int k = 0; k < B / 256; k++) {
        int i = t + k * 256;
        float mx = fmaxf(__int_as_float(__ldcg(&g_maxbits[i])), 1e-12f);
        float mn = fmaxf(__int_as_float(__ldcg(&g_minbits[i])), 1e-12f);
        tr += fmaxf(sqrtf(mx) - sqrtf(mn) + MARGIN, 0.0f);
        ce += __ldcg(&g_ce[i]);
    }
    s1[t] = tr; s2[t] = ce;
    __syncthreads();
    #pragma unroll
    for (int s = 128; s > 0; s >>= 1) {
        if (t < s) { s1[t] += s1[t + s]; s2[t] += s2[t + s]; }
        __syncthreads();
    }
    if (t == 0) out[0] = (s1[0] + s2[0]) * (1.0f / (float)B);
}

// ---------------------------------------------------------------------------
extern "C" void kernel_launch(void* const* d_in, const int* in_sizes, int n_in,
                              void* d_out, int out_size) {
    const float* emb    = (const float*)d_in[0];
    const int*   labels = (const int*)d_in[1];
    const float* fcw    = (const float*)d_in[2];
    const float* fcb    = (const float*)d_in[3];
    float*       out    = (float*)d_out;

    cudaFuncSetAttribute(fused_kernel,
                         cudaFuncAttributeMaxDynamicSharedMemorySize, PW_SMEM);

    void* p_done;
    cudaGetSymbolAddress(&p_done, g_done);
    cudaMemsetAsync(p_done, 0x00, sizeof(unsigned));

    prep_kernel<<<(B * 32) / 256, 256>>>(emb, labels);
    fused_kernel<<<TOTAL_BLOCKS, 256, PW_SMEM>>>(emb, fcw, fcb, out);
}

// round 9
// speedup vs baseline: 1.1836x; 1.1499x over previous
#include <cuda_runtime.h>
#include <cuda_bf16.h>
#include <math.h>

// Problem constants
#define B 4096
#define K 128
#define C 100
#define MARGIN 0.3f

#define PW_BLOCKS ((32 * 33) / 2)   // 528 triangular 128x128 tiles
#define CE_ROWS 16
#define CE_BLOCKS (B / CE_ROWS)     // 256

typedef unsigned long long u64;

// Scratch (device globals)
__device__ int      g_maxbits[B];
__device__ int      g_minbits[B];
__device__ float    g_sq[B];
__device__ float    g_ce[B];
__device__ int      g_lab[B];
__device__ float    g_part_tr[16];
__device__ float    g_part_ce[16];
__device__ unsigned g_rdone;

// ---------------------------------------------------------------------------
// Kernel 1: squared norms + init + labels (int32).  (exact R6 version)
// ---------------------------------------------------------------------------
__global__ void prep_kernel(const float* __restrict__ emb,
                            const int* __restrict__ labels) {
    int warp = (blockIdx.x * blockDim.x + threadIdx.x) >> 5;
    int lane = threadIdx.x & 31;
    if (warp >= B) return;
    float4 v = reinterpret_cast<const float4*>(emb)[warp * 32 + lane];
    float s = v.x * v.x + v.y * v.y + v.z * v.z + v.w * v.w;
    #pragma unroll
    for (int m = 16; m; m >>= 1) s += __shfl_xor_sync(0xffffffffu, s, m);
    if (lane == 0) {
        g_sq[warp]      = s;
        g_maxbits[warp] = 0;
        g_minbits[warp] = 0x7f800000;   // +inf
        g_lab[warp]     = labels[warp];
    }
}

// ---------------------------------------------------------------------------
// Pairwise body (exact R6 version — DO NOT PERTURB).
// ---------------------------------------------------------------------------
#define PAD 130
#define PW_SMEM (2 * 128 * PAD * 4)

__device__ __forceinline__ void pairwise_body(float* sm, const float* __restrict__ emb,
                                              int bid) {
    float* As = sm;                 // [128][130]
    float* Bs = sm + 128 * PAD;     // [128][130]
    __shared__ int   labA[128], labB[128];
    __shared__ float sqA[128], sqB[128];
    __shared__ float s_cp[8][128], s_cn[8][128];

    // Triangular block decode: by <= bx
    float tf = sqrtf(8.0f * (float)bid + 1.0f);
    int bx = (int)((tf - 1.0f) * 0.5f);
    while ((bx + 1) * (bx + 2) / 2 <= bid) bx++;
    while (bx * (bx + 1) / 2 > bid) bx--;
    int by = bid - bx * (bx + 1) / 2;
    const bool diag = (by == bx);

    const int tx  = threadIdx.x & 15, ty = threadIdx.x >> 4;
    const int tid = threadIdx.x;
    const int wid = tid >> 5;
    const int i0  = by * 128;
    const int j0  = bx * 128;

    const float4* e4 = reinterpret_cast<const float4*>(emb);
    #pragma unroll
    for (int f = tid; f < 128 * 32; f += 256) {
        int row = f >> 5, c4 = f & 31;
        float4 va = e4[(i0 + row) * 32 + c4];
        float4 vb = e4[(j0 + row) * 32 + c4];
        float2* ap = reinterpret_cast<float2*>(&As[row * PAD + c4 * 4]);
        ap[0] = make_float2(va.x, va.y);
        ap[1] = make_float2(va.z, va.w);
        float2* bp = reinterpret_cast<float2*>(&Bs[row * PAD + c4 * 4]);
        bp[0] = make_float2(vb.x, vb.y);
        bp[1] = make_float2(vb.z, vb.w);
    }
    if (tid < 128) {
        labA[tid] = g_lab[i0 + tid];
        labB[tid] = g_lab[j0 + tid];
        sqA[tid]  = g_sq[i0 + tid];
        sqB[tid]  = g_sq[j0 + tid];
    }
    __syncthreads();

    u64 acc[8][8];
    #pragma unroll
    for (int q = 0; q < 8; q++)
        #pragma unroll
        for (int r = 0; r < 8; r++) acc[q][r] = 0ull;

    #pragma unroll 2
    for (int kp = 0; kp < K / 2; kp++) {
        u64 a2[8], b2[8];
        #pragma unroll
        for (int q = 0; q < 8; q++)
            a2[q] = *reinterpret_cast<const u64*>(&As[(ty + 16 * q) * PAD + 2 * kp]);
        #pragma unroll
        for (int r = 0; r < 8; r++)
            b2[r] = *reinterpret_cast<const u64*>(&Bs[(tx + 16 * r) * PAD + 2 * kp]);
        #pragma unroll
        for (int q = 0; q < 8; q++)
            #pragma unroll
            for (int r = 0; r < 8; r++)
                asm("fma.rn.f32x2 %0, %1, %2, %0;"
                    : "+l"(acc[q][r]) : "l"(a2[q]), "l"(b2[r]));
    }

    const float INF = __int_as_float(0x7f800000);
    float colPos[8], colNeg[8];
    #pragma unroll
    for (int r = 0; r < 8; r++) { colPos[r] = 0.0f; colNeg[r] = INF; }

    #pragma unroll
    for (int q = 0; q < 8; q++) {
        int   i  = ty + 16 * q;
        int   li = labA[i];
        float si = sqA[i];
        float pos = 0.0f, neg = INF;
        #pragma unroll
        for (int r = 0; r < 8; r++) {
            int   j   = tx + 16 * r;
            float glo = __uint_as_float((unsigned)(acc[q][r] & 0xffffffffull));
            float ghi = __uint_as_float((unsigned)(acc[q][r] >> 32));
            float d2  = fmaxf(si + sqB[j] - 2.0f * (glo + ghi), 0.0f);
            bool same = (labB[j] == li);
            if (same) { pos = fmaxf(pos, d2); colPos[r] = fmaxf(colPos[r], d2); }
            else      { neg = fminf(neg, d2); colNeg[r] = fminf(colNeg[r], d2); }
        }
        #pragma unroll
        for (int m = 8; m; m >>= 1) {
            pos = fmaxf(pos, __shfl_xor_sync(0xffffffffu, pos, m));
            neg = fminf(neg, __shfl_xor_sync(0xffffffffu, neg, m));
        }
        if (tx == 0) {
            atomicMax(&g_maxbits[i0 + i], __float_as_int(pos));
            atomicMin(&g_minbits[i0 + i], __float_as_int(neg));
        }
    }

    if (!diag) {
        #pragma unroll
        for (int r = 0; r < 8; r++) {
            float p = fmaxf(colPos[r], __shfl_xor_sync(0xffffffffu, colPos[r], 16));
            float n = fminf(colNeg[r], __shfl_xor_sync(0xffffffffu, colNeg[r], 16));
            if ((tid & 16) == 0) {
                s_cp[wid][r * 16 + tx] = p;
                s_cn[wid][r * 16 + tx] = n;
            }
        }
        __syncthreads();
        if (tid < 128) {
            float p = s_cp[0][tid], n = s_cn[0][tid];
            #pragma unroll
            for (int w = 1; w < 8; w++) {
                p = fmaxf(p, s_cp[w][tid]);
                n = fminf(n, s_cn[w][tid]);
            }
            atomicMax(&g_maxbits[j0 + tid], __float_as_int(p));
            atomicMin(&g_minbits[j0 + tid], __float_as_int(n));
        }
    }
}

// ---------------------------------------------------------------------------
// CE body (exact R6 version).
// ---------------------------------------------------------------------------
__device__ __forceinline__ void ce_body(float* sm, const float* __restrict__ emb,
                                        const float* __restrict__ w,
                                        const float* __restrict__ bias, int bid) {
    float* w_s = sm;                        // [100][133]
    float* e_s = sm + C * 133;              // [16][129]
    float* lg  = e_s + CE_ROWS * 129;       // [16][100]

    int tid = threadIdx.x;
    int r0  = bid * CE_ROWS;

    for (int f = tid; f < C * K; f += 256) {
        int c = f >> 7, k = f & 127;
        w_s[c * 133 + k] = w[f];
    }
    for (int f = tid; f < CE_ROWS * K; f += 256) {
        int r = f >> 7, k = f & 127;
        e_s[r * 129 + k] = emb[(r0 + r) * K + k];
    }
    __syncthreads();

    int grp = tid >> 7;
    int c   = tid & 127;
    if (c < C) {
        float accv[8];
        float bv = bias[c];
        #pragma unroll
        for (int r = 0; r < 8; r++) accv[r] = bv;
        for (int k = 0; k < K; k++) {
            float wv = w_s[c * 133 + k];
            #pragma unroll
            for (int r = 0; r < 8; r++)
                accv[r] = fmaf(wv, e_s[(grp * 8 + r) * 129 + k], accv[r]);
        }
        #pragma unroll
        for (int r = 0; r < 8; r++) lg[(grp * 8 + r) * C + c] = accv[r];
    }
    __syncthreads();

    if (tid < CE_ROWS) {
        int   lab = g_lab[r0 + tid];
        float m = -1e30f;
        for (int cc = 0; cc < C; cc++) m = fmaxf(m, lg[tid * C + cc]);
        float s = 0.0f;
        for (int cc = 0; cc < C; cc++) s += expf(lg[tid * C + cc] - m);
        g_ce[r0 + tid] = m + logf(s) - lg[tid * C + lab];
    }
}

// Fused kernel — exact R6 form, NO tail.
__global__ void __launch_bounds__(256, 1)
fused_kernel(const float* __restrict__ emb, const float* __restrict__ w,
             const float* __restrict__ bias) {
    extern __shared__ float sm[];
    if (blockIdx.x < PW_BLOCKS) pairwise_body(sm, emb, blockIdx.x);
    else                        ce_body(sm, emb, w, bias, blockIdx.x - PW_BLOCKS);
}

// ---------------------------------------------------------------------------
// Single reduce kernel: 16 blocks x 256 threads; last block combines the 16
// partials with a fixed shuffle tree (deterministic).
// ---------------------------------------------------------------------------
__global__ void reduce_kernel(float* __restrict__ out) {
    __shared__ float    s1[256], s2[256];
    __shared__ unsigned s_last;
    int t = threadIdx.x;
    int i = blockIdx.x * 256 + t;
    float mx = fmaxf(__int_as_float(g_maxbits[i]), 1e-12f);
    float mn = fmaxf(__int_as_float(g_minbits[i]), 1e-12f);
    s1[t] = fmaxf(sqrtf(mx) - sqrtf(mn) + MARGIN, 0.0f);
    s2[t] = g_ce[i];
    __syncthreads();
    #pragma unroll
    for (int s = 128; s > 0; s >>= 1) {
        if (t < s) { s1[t] += s1[t + s]; s2[t] += s2[t + s]; }
        __syncthreads();
    }
    if (t == 0) {
        g_part_tr[blockIdx.x] = s1[0];
        g_part_ce[blockIdx.x] = s2[0];
        __threadfence();
        s_last = (atomicAdd(&g_rdone, 1u) == 15u) ? 1u : 0u;
    }
    __syncthreads();
    if (s_last && t < 32) {
        float v = 0.0f;
        if (t < 16) v = __ldcg(&g_part_tr[t]) + __ldcg(&g_part_ce[t]);
        #pragma unroll
        for (int m = 8; m; m >>= 1) v += __shfl_xor_sync(0xffffffffu, v, m);
        if (t == 0) out[0] = v * (1.0f / (float)B);
    }
}

// ---------------------------------------------------------------------------
extern "C" void kernel_launch(void* const* d_in, const int* in_sizes, int n_in,
                              void* d_out, int out_size) {
    const float* emb    = (const float*)d_in[0];
    const int*   labels = (const int*)d_in[1];
    const float* fcw    = (const float*)d_in[2];
    const float* fcb    = (const float*)d_in[3];
    float*       out    = (float*)d_out;

    cudaFuncSetAttribute(fused_kernel,
                         cudaFuncAttributeMaxDynamicSharedMemorySize, PW_SMEM);

    void* p_rdone;
    cudaGetSymbolAddress(&p_rdone, g_rdone);
    cudaMemsetAsync(p_rdone, 0x00, sizeof(unsigned));

    prep_kernel<<<(B * 32) / 256, 256>>>(emb, labels);
    fused_kernel<<<PW_BLOCKS + CE_BLOCKS, 256, PW_SMEM>>>(emb, fcw, fcb);
    reduce_kernel<<<16, 256>>>(out);
}